// round 16
// baseline (speedup 1.0000x reference)
#include <cuda_runtime.h>
#include <math.h>

#define NN 62
#define BG 512
#define FIN 128
#define HH 64
#define CC 3
#define TRIL ((NN*(NN+1))/2)

// Producer -> consumer handoff (persists across graph replays; contents are
// identical every replay, so concurrent same-value rewrites are benign).
__device__ float g_W1Tp[HH*132]; // W1 padded copy [h][132] (cols 128..131 = 0)
__device__ float g_A2p[64*68];   // A^2 padded [64][68], zeros outside 62x62
__device__ int   g_flag_w;      // set after g_W1Tp ready
__device__ int   g_flag_a;      // set after g_A2p ready

// ---------------------------------------------------------------------------
// f32x2 packed helpers
// ---------------------------------------------------------------------------
__device__ __forceinline__ unsigned long long packf2(float lo, float hi) {
    unsigned long long r;
    asm("mov.b64 %0, {%1, %2};" : "=l"(r) : "f"(lo), "f"(hi));
    return r;
}
__device__ __forceinline__ void unpack2(unsigned long long v, float& lo, float& hi) {
    asm("mov.b64 {%0, %1}, %2;" : "=f"(lo), "=f"(hi) : "l"(v));
}
__device__ __forceinline__ void fma2(unsigned long long& d,
                                     unsigned long long a, unsigned long long b) {
    asm("fma.rn.f32x2 %0, %1, %2, %0;" : "+l"(d) : "l"(a), "l"(b));
}

// ---------------------------------------------------------------------------
// Fused single-launch kernel. grid = 513:
//   block 0      : producer (W1 padded copy -> g_W1Tp; A -> A^2 -> g_A2p)
//   blocks 1..512: per-graph fused pipeline. 4n x 4h per-thread tiles,
//                  f32x2 packed along the REDUCTION dim (k / m): both FFMA2
//                  operands come straight from 16B smem loads, no pack MOVs.
//                  h-tile = {hg, hg+16, hg+32, hg+48} for low-conflict rows.
//
// consumer smem aliasing (floats), 16968 total (67.9 KB -> 3 CTAs/SM):
//   region0 [64*132]: Xs during GEMM1; Zt[64][68] (h-major Z) after, in the
//                     first 4352 floats (barrier separates X reads / Zt writes)
//   region1 [64*132]: Wst (W1 rows, stride 132) during GEMM1;
//                     A2s[64][68] + part[16][64] after
//   tail    [72]    : pooled[64] + red[8]
// ---------------------------------------------------------------------------
#define XS_F   (64*132)
#define WS_F   (64*132)
#define SMEM_FLOATS (XS_F + WS_F + 64 + 8)
#define SMEM_BYTES  (SMEM_FLOATS * 4)

__global__ void __launch_bounds__(256, 3) gcn_fused_kernel(
    const float* __restrict__ x,
    const float* __restrict__ tril,
    const float* __restrict__ W1,
    const float* __restrict__ b1,
    const float* __restrict__ W2,
    const float* __restrict__ b2,
    float* __restrict__ out)
{
    extern __shared__ float sm[];
    int t = threadIdx.x;

    // ===================== PRODUCER (block 0) =====================
    if (blockIdx.x == 0) {
        // 1) W1 padded copy first: consumers need it early
        for (int idx = t; idx < HH*132; idx += 256) {
            int h = idx / 132, k = idx - h*132;
            g_W1Tp[idx] = (k < FIN) ? W1[h*FIN + k] : 0.f;
        }
        __threadfence();
        __syncthreads();
        if (t == 0) atomicExch(&g_flag_w, 1);

        // 2) A -> A^2
        float* Ws   = sm;                 // [62][62]
        float* Af   = sm + NN*NN;         // [62][62]
        float* dinv = sm + 2*NN*NN;       // [62]

        for (int p = t; p < TRIL; p += 256) {
            int i = (int)((sqrtf(8.0f*(float)p + 1.0f) - 1.0f) * 0.5f);
            while ((i+1)*(i+2)/2 <= p) i++;
            while (i*(i+1)/2 > p) i--;
            int j = p - i*(i+1)/2;
            float v = tril[p];
            Ws[i*NN+j] = v;
            Ws[j*NN+i] = v;
        }
        __syncthreads();
        if (t < NN) {
            float s = 0.f;
            for (int j = 0; j < NN; ++j) s += fabsf(Ws[t*NN+j]);
            dinv[t] = (s > 0.f) ? rsqrtf(s) : 0.f;
        }
        __syncthreads();
        for (int p = t; p < NN*NN; p += 256) {
            int i = p / NN, j = p % NN;
            Af[p] = dinv[i] * Ws[p] * dinv[j];
        }
        __syncthreads();
        for (int p = t; p < 64*68; p += 256) {
            int r = p / 68, c = p % 68;
            float s = 0.f;
            if (r < NN && c < NN) {
                for (int m = 0; m < NN; ++m) s += Af[r*NN + m] * Af[m*NN + c];
            }
            g_A2p[p] = s;
        }
        __threadfence();
        __syncthreads();
        if (t == 0) atomicExch(&g_flag_a, 1);
        return;
    }

    // ===================== CONSUMERS =====================
    float* Xs     = sm;                 // [64][132]; Zt[64][68] after GEMM1
    float* Zt     = sm;                 // h-major Z, stride 68
    float* Wst    = sm + XS_F;          // [64][132] W1 rows during GEMM1
    float* A2s    = Wst;                // [64][68]  after GEMM1 (aliased)
    float* part   = Wst + 64*68;        // [16][64]  (aliased)
    float* pooled = sm + XS_F + WS_F;   // [64]
    float* red    = pooled + HH;        // [8]

    int g = blockIdx.x - 1;
    const float* xg = x + (size_t)g * NN * FIN;

    // ---- stage X (coalesced float4); overlaps producer's W1 copy ----
    for (int e = t; e < NN*32; e += 256) {
        int row = e >> 5, c4 = e & 31;
        float4 v = *(const float4*)(xg + row*FIN + 4*c4);
        *(float4*)(Xs + row*132 + 4*c4) = v;
    }
    // rows 62,63: cols 0..127 read in GEMM1 -> zero them
    for (int p = t; p < 2*FIN; p += 256) Xs[62*132 + (p>>7)*132 + (p&127)] = 0.f;

    // ---- wait for W1 copy, then conflict-free float4 copy into smem ----
    if (t == 0) {
        while (atomicAdd(&g_flag_w, 0) == 0) __nanosleep(32);
        __threadfence();
    }
    __syncthreads();
    for (int e = t; e < (HH*132)/4; e += 256)
        *(float4*)(Wst + 4*e) = *(const float4*)(g_W1Tp + 4*e);
    __syncthreads();

    int hg = t & 15;        // h-tile: hg, hg+16, hg+32, hg+48
    int ng = t >> 4;        // n-tile: 4*ng .. 4*ng+3
    int h1 = hg + 16, h2 = hg + 32, h3 = hg + 48;

    // ---- GEMM1: Z = X @ W1^T, packed along k ----
    unsigned long long acc[4][4];   // [j: h][i: node], lo=even-k, hi=odd-k
    {
        #pragma unroll
        for (int j = 0; j < 4; ++j)
            #pragma unroll
            for (int i = 0; i < 4; ++i) acc[j][i] = 0ull;

        const float* xr0 = Xs + (4*ng+0)*132;
        const float* xr1 = Xs + (4*ng+1)*132;
        const float* xr2 = Xs + (4*ng+2)*132;
        const float* xr3 = Xs + (4*ng+3)*132;
        const float* wr0 = Wst + hg*132;
        const float* wr1 = Wst + h1*132;
        const float* wr2 = Wst + h2*132;
        const float* wr3 = Wst + h3*132;

        #pragma unroll 4
        for (int k = 0; k < FIN; k += 4) {
            // 8 LDS.128, batched (MLP 8); each .x/.y is a ready f32x2 pair
            ulonglong2 w0 = *(const ulonglong2*)(wr0 + k);
            ulonglong2 w1 = *(const ulonglong2*)(wr1 + k);
            ulonglong2 w2 = *(const ulonglong2*)(wr2 + k);
            ulonglong2 w3 = *(const ulonglong2*)(wr3 + k);
            ulonglong2 x0 = *(const ulonglong2*)(xr0 + k);
            ulonglong2 x1 = *(const ulonglong2*)(xr1 + k);
            ulonglong2 x2 = *(const ulonglong2*)(xr2 + k);
            ulonglong2 x3 = *(const ulonglong2*)(xr3 + k);
            fma2(acc[0][0], w0.x, x0.x); fma2(acc[0][1], w0.x, x1.x);
            fma2(acc[0][2], w0.x, x2.x); fma2(acc[0][3], w0.x, x3.x);
            fma2(acc[1][0], w1.x, x0.x); fma2(acc[1][1], w1.x, x1.x);
            fma2(acc[1][2], w1.x, x2.x); fma2(acc[1][3], w1.x, x3.x);
            fma2(acc[2][0], w2.x, x0.x); fma2(acc[2][1], w2.x, x1.x);
            fma2(acc[2][2], w2.x, x2.x); fma2(acc[2][3], w2.x, x3.x);
            fma2(acc[3][0], w3.x, x0.x); fma2(acc[3][1], w3.x, x1.x);
            fma2(acc[3][2], w3.x, x2.x); fma2(acc[3][3], w3.x, x3.x);
            fma2(acc[0][0], w0.y, x0.y); fma2(acc[0][1], w0.y, x1.y);
            fma2(acc[0][2], w0.y, x2.y); fma2(acc[0][3], w0.y, x3.y);
            fma2(acc[1][0], w1.y, x0.y); fma2(acc[1][1], w1.y, x1.y);
            fma2(acc[1][2], w1.y, x2.y); fma2(acc[1][3], w1.y, x3.y);
            fma2(acc[2][0], w2.y, x0.y); fma2(acc[2][1], w2.y, x1.y);
            fma2(acc[2][2], w2.y, x2.y); fma2(acc[2][3], w2.y, x3.y);
            fma2(acc[3][0], w3.y, x0.y); fma2(acc[3][1], w3.y, x1.y);
            fma2(acc[3][2], w3.y, x2.y); fma2(acc[3][3], w3.y, x3.y);
        }
    }

    // ---- wait A^2; one barrier ends all X/W reads, then Zt stores + A2 copy
    if (t == 0) {
        while (atomicAdd(&g_flag_a, 0) == 0) __nanosleep(64);
        __threadfence();
    }
    __syncthreads();   // GEMM1 reads done + flag observed (accs live in regs)

    #pragma unroll
    for (int j = 0; j < 4; ++j) {
        int h = hg + 16*j;
        #pragma unroll
        for (int i = 0; i < 4; ++i) {
            float lo, hi; unpack2(acc[j][i], lo, hi);
            Zt[h*68 + 4*ng + i] = lo + hi;
        }
    }
    for (int e = t; e < (64*68)/4; e += 256)
        *(float4*)(A2s + 4*e) = *(const float4*)(g_A2p + 4*e);
    // b1 for this thread's h-tile (overlaps with barrier)
    float bj0 = b1[hg], bj1 = b1[h1], bj2 = b1[h2], bj3 = b1[h3];
    __syncthreads();

    // ---- GEMM2: Y = A2 @ Z + b1, packed along m ----
    unsigned long long a2c[4][4];
    {
        a2c[0][0] = packf2(bj0, 0.f); a2c[1][0] = packf2(bj1, 0.f);
        a2c[2][0] = packf2(bj2, 0.f); a2c[3][0] = packf2(bj3, 0.f);
        #pragma unroll
        for (int j = 0; j < 4; ++j)
            #pragma unroll
            for (int i = 1; i < 4; ++i) a2c[j][i] = a2c[j][0];

        const float* ar0 = A2s + (4*ng+0)*68;
        const float* ar1 = A2s + (4*ng+1)*68;
        const float* ar2 = A2s + (4*ng+2)*68;
        const float* ar3 = A2s + (4*ng+3)*68;
        const float* zr0 = Zt + hg*68;
        const float* zr1 = Zt + h1*68;
        const float* zr2 = Zt + h2*68;
        const float* zr3 = Zt + h3*68;

        #pragma unroll 4
        for (int m = 0; m < 64; m += 4) {
            ulonglong2 a0 = *(const ulonglong2*)(ar0 + m);
            ulonglong2 a1 = *(const ulonglong2*)(ar1 + m);
            ulonglong2 a2 = *(const ulonglong2*)(ar2 + m);
            ulonglong2 a3 = *(const ulonglong2*)(ar3 + m);
            ulonglong2 z0 = *(const ulonglong2*)(zr0 + m);
            ulonglong2 z1 = *(const ulonglong2*)(zr1 + m);
            ulonglong2 z2 = *(const ulonglong2*)(zr2 + m);
            ulonglong2 z3 = *(const ulonglong2*)(zr3 + m);
            fma2(a2c[0][0], z0.x, a0.x); fma2(a2c[0][1], z0.x, a1.x);
            fma2(a2c[0][2], z0.x, a2.x); fma2(a2c[0][3], z0.x, a3.x);
            fma2(a2c[1][0], z1.x, a0.x); fma2(a2c[1][1], z1.x, a1.x);
            fma2(a2c[1][2], z1.x, a2.x); fma2(a2c[1][3], z1.x, a3.x);
            fma2(a2c[2][0], z2.x, a0.x); fma2(a2c[2][1], z2.x, a1.x);
            fma2(a2c[2][2], z2.x, a2.x); fma2(a2c[2][3], z2.x, a3.x);
            fma2(a2c[3][0], z3.x, a0.x); fma2(a2c[3][1], z3.x, a1.x);
            fma2(a2c[3][2], z3.x, a2.x); fma2(a2c[3][3], z3.x, a3.x);
            fma2(a2c[0][0], z0.y, a0.y); fma2(a2c[0][1], z0.y, a1.y);
            fma2(a2c[0][2], z0.y, a2.y); fma2(a2c[0][3], z0.y, a3.y);
            fma2(a2c[1][0], z1.y, a0.y); fma2(a2c[1][1], z1.y, a1.y);
            fma2(a2c[1][2], z1.y, a2.y); fma2(a2c[1][3], z1.y, a3.y);
            fma2(a2c[2][0], z2.y, a0.y); fma2(a2c[2][1], z2.y, a1.y);
            fma2(a2c[2][2], z2.y, a2.y); fma2(a2c[2][3], z2.y, a3.y);
            fma2(a2c[3][0], z3.y, a0.y); fma2(a2c[3][1], z3.y, a1.y);
            fma2(a2c[3][2], z3.y, a2.y); fma2(a2c[3][3], z3.y, a3.y);
        }
    }

    // relu + pool over this thread's valid nodes, 4 scattered h each
    {
        float ps[4] = {0.f, 0.f, 0.f, 0.f};
        #pragma unroll
        for (int i = 0; i < 4; ++i) {
            if (4*ng + i < NN) {
                #pragma unroll
                for (int j = 0; j < 4; ++j) {
                    float lo, hi; unpack2(a2c[j][i], lo, hi);
                    ps[j] += fmaxf(lo + hi, 0.f);
                }
            }
        }
        #pragma unroll
        for (int j = 0; j < 4; ++j) part[ng*64 + hg + 16*j] = ps[j];
    }
    __syncthreads();

    if (t < HH) {
        float s = 0.f;
        #pragma unroll
        for (int gg = 0; gg < 16; ++gg) s += part[gg*64 + t];
        pooled[t] = s;
    }
    __syncthreads();

    // ---- logits = pooled @ W2^T + b2 ----
    if (t < CC) {
        float s = b2[t];
        const float* w2r = W2 + t*HH;
        #pragma unroll 8
        for (int hh = 0; hh < HH; ++hh) s = fmaf(w2r[hh], pooled[hh], s);
        red[t] = s;
    }
    __syncthreads();

    // ---- outputs ----
    if (t < HH) out[(size_t)g*HH + t] = pooled[t];
    if (t == 0) {
        float mx = fmaxf(red[0], fmaxf(red[1], red[2]));
        float sum = expf(red[0]-mx) + expf(red[1]-mx) + expf(red[2]-mx);
        red[4] = mx + logf(sum);
    }
    __syncthreads();
    if (t < CC)
        out[(size_t)BG*HH + (size_t)g*CC + t] = red[t] - red[4];
}

// ---------------------------------------------------------------------------
extern "C" void kernel_launch(void* const* d_in, const int* in_sizes, int n_in,
                              void* d_out, int out_size) {
    const float* x    = (const float*)d_in[0];
    const float* tril = (const float*)d_in[1];
    const float* W1   = (const float*)d_in[2];
    const float* b1   = (const float*)d_in[3];
    const float* W2   = (const float*)d_in[4];
    const float* b2   = (const float*)d_in[5];
    float* out = (float*)d_out;

    cudaFuncSetAttribute(gcn_fused_kernel,
                         cudaFuncAttributeMaxDynamicSharedMemorySize, SMEM_BYTES);

    gcn_fused_kernel<<<BG + 1, 256, SMEM_BYTES>>>(x, tril, W1, b1, W2, b2, out);
}